// round 3
// baseline (speedup 1.0000x reference)
#include <cuda_runtime.h>
#include <math.h>

#define SEQ     4096
#define DIM     1024
#define NH      16
#define HD      64
#define HIDDEN  4096
#define EPSV    1e-6f

// ---------------- scratch (static device globals; no allocation) ----------------
__device__ float d_xn  [SEQ * DIM];
__device__ float d_q   [SEQ * DIM];
__device__ float d_k   [SEQ * DIM];
__device__ float d_v   [SEQ * DIM];
__device__ float d_attn[SEQ * DIM];
__device__ float d_h   [SEQ * DIM];
__device__ float d_hn  [SEQ * DIM];
__device__ float d_g1  [SEQ * HIDDEN];
__device__ float d_g3  [SEQ * HIDDEN];

// ---------------- rmsnorm: one block per row ----------------
__global__ void rmsnorm_kernel(const float* __restrict__ x,
                               const float* __restrict__ g,
                               float* __restrict__ o)
{
    int row = blockIdx.x;
    int tid = threadIdx.x;                       // 256 threads, 4 floats each
    const float4* xr = (const float4*)(x + (size_t)row * DIM);
    float4 v = xr[tid];
    float s = v.x * v.x + v.y * v.y + v.z * v.z + v.w * v.w;
    #pragma unroll
    for (int off = 16; off; off >>= 1) s += __shfl_xor_sync(0xffffffffu, s, off);

    __shared__ float red[8];
    __shared__ float rinv;
    if ((tid & 31) == 0) red[tid >> 5] = s;
    __syncthreads();
    if (tid == 0) {
        float t = 0.f;
        #pragma unroll
        for (int i = 0; i < 8; i++) t += red[i];
        rinv = rsqrtf(t / (float)DIM + EPSV);
    }
    __syncthreads();
    float r = rinv;
    const float4* gr = (const float4*)g;
    float4 gv = gr[tid];
    float4 ov;
    ov.x = v.x * r * gv.x;
    ov.y = v.y * r * gv.y;
    ov.z = v.z * r * gv.z;
    ov.w = v.w * r * gv.w;
    ((float4*)(o + (size_t)row * DIM))[tid] = ov;
}

// ---------------- SGEMM: C[M,N] = A[M,K] @ B[N,K]^T (+ Cin) ----------------
// 128x128 tile, BK=16, 256 threads, 8x8 micro-tile
__global__ void __launch_bounds__(256) sgemm_tn(
    const float* __restrict__ A, const float* __restrict__ B,
    const float* __restrict__ Cin, float* __restrict__ C,
    int M, int N, int K)
{
    const int BM = 128, BN = 128, BK = 16, LDS = 132;
    __shared__ float As[BK * LDS];
    __shared__ float Bs[BK * LDS];

    int tid = threadIdx.x;
    int bm = blockIdx.y * BM;
    int bn = blockIdx.x * BN;
    int tr = (tid >> 4) << 3;   // 0..120
    int tc = (tid & 15) << 3;   // 0..120

    float acc[8][8];
    #pragma unroll
    for (int i = 0; i < 8; i++)
        #pragma unroll
        for (int j = 0; j < 8; j++) acc[i][j] = 0.f;

    const float* Aptr = A + (size_t)bm * K;
    const float* Bptr = B + (size_t)bn * K;

    for (int k0 = 0; k0 < K; k0 += BK) {
        #pragma unroll
        for (int i = 0; i < 2; i++) {
            int f  = tid + (i << 8);      // 0..511 float4 slots
            int r  = f >> 2;              // row in tile 0..127
            int kq = (f & 3) << 2;        // k offset 0,4,8,12
            float4 va = *(const float4*)(Aptr + (size_t)r * K + k0 + kq);
            As[(kq + 0) * LDS + r] = va.x;
            As[(kq + 1) * LDS + r] = va.y;
            As[(kq + 2) * LDS + r] = va.z;
            As[(kq + 3) * LDS + r] = va.w;
            float4 vb = *(const float4*)(Bptr + (size_t)r * K + k0 + kq);
            Bs[(kq + 0) * LDS + r] = vb.x;
            Bs[(kq + 1) * LDS + r] = vb.y;
            Bs[(kq + 2) * LDS + r] = vb.z;
            Bs[(kq + 3) * LDS + r] = vb.w;
        }
        __syncthreads();
        #pragma unroll
        for (int k = 0; k < BK; k++) {
            float a[8], b[8];
            #pragma unroll
            for (int i = 0; i < 8; i++) a[i] = As[k * LDS + tr + i];
            #pragma unroll
            for (int j = 0; j < 8; j++) b[j] = Bs[k * LDS + tc + j];
            #pragma unroll
            for (int i = 0; i < 8; i++)
                #pragma unroll
                for (int j = 0; j < 8; j++)
                    acc[i][j] += a[i] * b[j];
        }
        __syncthreads();
    }

    #pragma unroll
    for (int i = 0; i < 8; i++) {
        size_t row = (size_t)(bm + tr + i);
        #pragma unroll
        for (int j = 0; j < 8; j += 4) {
            float4 o;
            o.x = acc[i][j + 0]; o.y = acc[i][j + 1];
            o.z = acc[i][j + 2]; o.w = acc[i][j + 3];
            size_t off = row * N + bn + tc + j;
            if (Cin) {
                float4 ci = *(const float4*)(Cin + off);
                o.x += ci.x; o.y += ci.y; o.z += ci.z; o.w += ci.w;
            }
            *(float4*)(C + off) = o;
        }
    }
}

// ---------------- RoPE (in-place on q and k) ----------------
__global__ void rope_kernel(float* __restrict__ q, float* __restrict__ k)
{
    int idx = blockIdx.x * blockDim.x + threadIdx.x;   // SEQ*NH*32 total
    int i = idx & 31;            // pair index 0..31
    int h = (idx >> 5) & (NH - 1);
    int s = idx >> 9;
    // inv freq computed in double, rounded to fp32 (matches XLA fp32 pow to ~1ulp)
    float inv = (float)pow(10000.0, -(double)(2 * i) / (double)HD);
    float ang = (float)s * inv;
    float c, sn;
    sincosf(ang, &sn, &c);
    size_t base = (size_t)s * DIM + h * HD + 2 * i;
    float qr = q[base], qi = q[base + 1];
    q[base]     = qr * c - qi * sn;
    q[base + 1] = qr * sn + qi * c;
    float kr = k[base], ki = k[base + 1];
    k[base]     = kr * c - ki * sn;
    k[base + 1] = kr * sn + ki * c;
}

// ---------------- fused attention: 1 thread = 1 query row ----------------
#define BQ 128
#define BKEY 64
__global__ void __launch_bounds__(BQ) attn_kernel(
    const float* __restrict__ Q, const float* __restrict__ K,
    const float* __restrict__ V, float* __restrict__ O)
{
    int h   = blockIdx.y;
    int q0  = blockIdx.x * BQ;
    int tid = threadIdx.x;

    __shared__ float Ks[BKEY][HD];
    __shared__ float Vs[BKEY][HD];

    // load this thread's q row into registers
    float qv[HD];
    const float* qp = Q + (size_t)(q0 + tid) * DIM + h * HD;
    #pragma unroll
    for (int d = 0; d < HD; d += 4) {
        float4 t = *(const float4*)(qp + d);
        qv[d] = t.x; qv[d + 1] = t.y; qv[d + 2] = t.z; qv[d + 3] = t.w;
    }

    float m = -1e30f, l = 0.f;
    float acc[HD];
    #pragma unroll
    for (int d = 0; d < HD; d++) acc[d] = 0.f;

    for (int kt = 0; kt < SEQ; kt += BKEY) {
        __syncthreads();
        // stage K/V tiles: 64x64 floats each = 1024 float4, 8 per thread
        #pragma unroll
        for (int i = 0; i < 8; i++) {
            int f = tid + i * BQ;       // 0..1023
            int r = f >> 4;             // 0..63
            int c = (f & 15) << 2;      // 0..60
            size_t goff = (size_t)(kt + r) * DIM + h * HD + c;
            *(float4*)&Ks[r][c] = *(const float4*)(K + goff);
            *(float4*)&Vs[r][c] = *(const float4*)(V + goff);
        }
        __syncthreads();

        #pragma unroll 2
        for (int j = 0; j < BKEY; j++) {
            const float4* kr = (const float4*)&Ks[j][0];
            float s = 0.f;
            #pragma unroll
            for (int d4 = 0; d4 < HD / 4; d4++) {
                float4 kk = kr[d4];
                s += qv[4 * d4 + 0] * kk.x + qv[4 * d4 + 1] * kk.y
                   + qv[4 * d4 + 2] * kk.z + qv[4 * d4 + 3] * kk.w;
            }
            s *= 0.125f;                       // 1/sqrt(64)
            if (s > m) {                       // lazy rescale
                float corr = __expf(m - s);
                l *= corr;
                #pragma unroll
                for (int d = 0; d < HD; d++) acc[d] *= corr;
                m = s;
            }
            float p = __expf(s - m);
            l += p;
            const float4* vr = (const float4*)&Vs[j][0];
            #pragma unroll
            for (int d4 = 0; d4 < HD / 4; d4++) {
                float4 vv = vr[d4];
                acc[4 * d4 + 0] += p * vv.x;
                acc[4 * d4 + 1] += p * vv.y;
                acc[4 * d4 + 2] += p * vv.z;
                acc[4 * d4 + 3] += p * vv.w;
            }
        }
    }

    float li = 1.f / l;
    float* op = O + (size_t)(q0 + tid) * DIM + h * HD;
    #pragma unroll
    for (int d = 0; d < HD; d += 4) {
        float4 o;
        o.x = acc[d] * li; o.y = acc[d + 1] * li;
        o.z = acc[d + 2] * li; o.w = acc[d + 3] * li;
        *(float4*)(op + d) = o;
    }
}

// ---------------- swiglu: g1 = silu(g1) * g3 ----------------
__global__ void swiglu_kernel(float* __restrict__ g1, const float* __restrict__ g3)
{
    int i = blockIdx.x * blockDim.x + threadIdx.x;
    float4 a = ((const float4*)g1)[i];
    float4 b = ((const float4*)g3)[i];
    float4 o;
    o.x = a.x / (1.f + __expf(-a.x)) * b.x;
    o.y = a.y / (1.f + __expf(-a.y)) * b.y;
    o.z = a.z / (1.f + __expf(-a.z)) * b.z;
    o.w = a.w / (1.f + __expf(-a.w)) * b.w;
    ((float4*)g1)[i] = o;
}

// ---------------- launch ----------------
extern "C" void kernel_launch(void* const* d_in, const int* in_sizes, int n_in,
                              void* d_out, int out_size)
{
    const float* x  = (const float*)d_in[0];
    const float* wq = (const float*)d_in[1];
    const float* wk = (const float*)d_in[2];
    const float* wv = (const float*)d_in[3];
    const float* wo = (const float*)d_in[4];
    const float* w1 = (const float*)d_in[5];
    const float* w2 = (const float*)d_in[6];
    const float* w3 = (const float*)d_in[7];
    const float* ga = (const float*)d_in[8];
    const float* gf = (const float*)d_in[9];
    float* out = (float*)d_out;

    float *xn, *q, *k, *v, *attn, *h, *hn, *g1, *g3;
    cudaGetSymbolAddress((void**)&xn,   d_xn);
    cudaGetSymbolAddress((void**)&q,    d_q);
    cudaGetSymbolAddress((void**)&k,    d_k);
    cudaGetSymbolAddress((void**)&v,    d_v);
    cudaGetSymbolAddress((void**)&attn, d_attn);
    cudaGetSymbolAddress((void**)&h,    d_h);
    cudaGetSymbolAddress((void**)&hn,   d_hn);
    cudaGetSymbolAddress((void**)&g1,   d_g1);
    cudaGetSymbolAddress((void**)&g3,   d_g3);

    // 1. rmsnorm(x) -> xn
    rmsnorm_kernel<<<SEQ, 256>>>(x, ga, xn);

    // 2. q/k/v projections
    dim3 gproj(DIM / 128, SEQ / 128);
    sgemm_tn<<<gproj, 256>>>(xn, wq, nullptr, q, SEQ, DIM, DIM);
    sgemm_tn<<<gproj, 256>>>(xn, wk, nullptr, k, SEQ, DIM, DIM);
    sgemm_tn<<<gproj, 256>>>(xn, wv, nullptr, v, SEQ, DIM, DIM);

    // 3. RoPE in place
    rope_kernel<<<(SEQ * NH * (HD / 2)) / 256, 256>>>(q, k);

    // 4. attention
    dim3 gattn(SEQ / BQ, NH);
    attn_kernel<<<gattn, BQ>>>(q, k, v, attn);

    // 5. output projection + residual: h = x + attn @ wo^T
    sgemm_tn<<<gproj, 256>>>(attn, wo, x, h, SEQ, DIM, DIM);

    // 6. rmsnorm(h) -> hn
    rmsnorm_kernel<<<SEQ, 256>>>(h, gf, hn);

    // 7. FFN up projections
    dim3 gffn(HIDDEN / 128, SEQ / 128);
    sgemm_tn<<<gffn, 256>>>(hn, w1, nullptr, g1, SEQ, HIDDEN, DIM);
    sgemm_tn<<<gffn, 256>>>(hn, w3, nullptr, g3, SEQ, HIDDEN, DIM);

    // 8. swiglu gate
    swiglu_kernel<<<(SEQ * HIDDEN) / (256 * 4), 256>>>(g1, g3);

    // 9. down projection + residual: out = h + g1 @ w2^T
    sgemm_tn<<<gproj, 256>>>(g1, w2, h, out, SEQ, DIM, HIDDEN);
}

// round 17
// speedup vs baseline: 3.8754x; 3.8754x over previous
#include <cuda_runtime.h>
#include <cuda_fp16.h>
#include <math.h>
#include <stdint.h>

#define SEQ     4096
#define DIM     1024
#define NH      16
#define HD      64
#define HIDDEN  4096
#define EPSV    1e-6f

// ---------------- scratch (static device globals; no allocation) ----------------
__device__ float d_xn  [SEQ * DIM];
__device__ float d_q   [SEQ * DIM];
__device__ float d_k   [SEQ * DIM];
__device__ float d_v   [SEQ * DIM];
__device__ float d_attn[SEQ * DIM];
__device__ float d_h   [SEQ * DIM];
__device__ float d_hn  [SEQ * DIM];
__device__ float d_g1  [SEQ * HIDDEN];
__device__ float d_g3  [SEQ * HIDDEN];

// ---------------- mma.sync helpers (family-portable, legal on plain sm_103) ----------------
__device__ __forceinline__ void mma16816(float* c,
                                         uint32_t a0, uint32_t a1, uint32_t a2, uint32_t a3,
                                         uint32_t b0, uint32_t b1)
{
    asm volatile(
        "mma.sync.aligned.m16n8k16.row.col.f32.f16.f16.f32 "
        "{%0,%1,%2,%3}, {%4,%5,%6,%7}, {%8,%9}, {%0,%1,%2,%3};"
        : "+f"(c[0]), "+f"(c[1]), "+f"(c[2]), "+f"(c[3])
        : "r"(a0), "r"(a1), "r"(a2), "r"(a3), "r"(b0), "r"(b1));
}

__device__ __forceinline__ uint32_t pack_h2(float x, float y) {
    __half2 h = __floats2half2_rn(x, y);
    return *(uint32_t*)&h;
}

// =====================================================================
// Dense GEMM: C[M,N] = A[M,K] @ B[N,K]^T (+ Cin).  fp32 in/out, fp16 mma.
// 128x128 tile, BK=32, 256 threads (8 warps: 4m x 2n), warp tile 32x64.
// =====================================================================
#define GLDS 40   // padded row stride in halves (32 data + 8 pad)

__global__ void __launch_bounds__(256) gemm_f16(
    const float* __restrict__ A, const float* __restrict__ B,
    const float* __restrict__ Cin, float* __restrict__ C,
    int N, int K)
{
    __shared__ __half As[128 * GLDS];
    __shared__ __half Bs[128 * GLDS];

    int tid  = threadIdx.x;
    int lane = tid & 31;
    int warp = tid >> 5;
    int wm = warp & 3;          // m offset = 32*wm
    int wn = warp >> 2;         // n offset = 64*wn
    int g  = lane >> 2;         // 0..7
    int t4 = lane & 3;          // 0..3
    int bm = blockIdx.y * 128;
    int bn = blockIdx.x * 128;

    float acc[2][8][4];
    #pragma unroll
    for (int mi = 0; mi < 2; mi++)
        #pragma unroll
        for (int nj = 0; nj < 8; nj++)
            #pragma unroll
            for (int c = 0; c < 4; c++) acc[mi][nj][c] = 0.f;

    // per-thread load mapping: row = tid>>1 (0..127), seg = (tid&1)*16
    int lrow = tid >> 1;
    int lseg = (tid & 1) * 16;
    const float* Ald = A + (size_t)(bm + lrow) * K + lseg;
    const float* Bld = B + (size_t)(bn + lrow) * K + lseg;

    float4 ra[4], rb[4];
    #pragma unroll
    for (int i = 0; i < 4; i++) {
        ra[i] = *(const float4*)(Ald + i * 4);
        rb[i] = *(const float4*)(Bld + i * 4);
    }

    int NC = K >> 5;
    for (int ch = 0; ch < NC; ch++) {
        // convert + store current chunk
        #pragma unroll
        for (int i = 0; i < 4; i++) {
            uint2 ua, ub;
            ua.x = pack_h2(ra[i].x, ra[i].y);
            ua.y = pack_h2(ra[i].z, ra[i].w);
            ub.x = pack_h2(rb[i].x, rb[i].y);
            ub.y = pack_h2(rb[i].z, rb[i].w);
            *(uint2*)&As[lrow * GLDS + lseg + i * 4] = ua;
            *(uint2*)&Bs[lrow * GLDS + lseg + i * 4] = ub;
        }
        __syncthreads();

        // prefetch next chunk (overlaps the mma section)
        if (ch + 1 < NC) {
            int k0 = (ch + 1) << 5;
            #pragma unroll
            for (int i = 0; i < 4; i++) {
                ra[i] = *(const float4*)(Ald + k0 + i * 4);
                rb[i] = *(const float4*)(Bld + k0 + i * 4);
            }
        }

        #pragma unroll
        for (int ks = 0; ks < 32; ks += 16) {
            uint32_t a[2][4];
            #pragma unroll
            for (int mi = 0; mi < 2; mi++) {
                int rbse = wm * 32 + mi * 16;
                a[mi][0] = *(uint32_t*)&As[(rbse + g    ) * GLDS + ks     + 2 * t4];
                a[mi][1] = *(uint32_t*)&As[(rbse + g + 8) * GLDS + ks     + 2 * t4];
                a[mi][2] = *(uint32_t*)&As[(rbse + g    ) * GLDS + ks + 8 + 2 * t4];
                a[mi][3] = *(uint32_t*)&As[(rbse + g + 8) * GLDS + ks + 8 + 2 * t4];
            }
            #pragma unroll
            for (int nj = 0; nj < 8; nj++) {
                int nb = wn * 64 + nj * 8;
                uint32_t b0 = *(uint32_t*)&Bs[(nb + g) * GLDS + ks     + 2 * t4];
                uint32_t b1 = *(uint32_t*)&Bs[(nb + g) * GLDS + ks + 8 + 2 * t4];
                mma16816(acc[0][nj], a[0][0], a[0][1], a[0][2], a[0][3], b0, b1);
                mma16816(acc[1][nj], a[1][0], a[1][1], a[1][2], a[1][3], b0, b1);
            }
        }
        __syncthreads();
    }

    // epilogue
    #pragma unroll
    for (int mi = 0; mi < 2; mi++) {
        size_t r0 = (size_t)(bm + wm * 32 + mi * 16 + g);
        #pragma unroll
        for (int nj = 0; nj < 8; nj++) {
            size_t col = (size_t)(bn + wn * 64 + nj * 8 + 2 * t4);
            float2 v0, v1;
            v0.x = acc[mi][nj][0]; v0.y = acc[mi][nj][1];
            v1.x = acc[mi][nj][2]; v1.y = acc[mi][nj][3];
            size_t o0 = r0 * N + col, o1 = (r0 + 8) * N + col;
            if (Cin) {
                float2 c0 = *(const float2*)(Cin + o0);
                float2 c1 = *(const float2*)(Cin + o1);
                v0.x += c0.x; v0.y += c0.y;
                v1.x += c1.x; v1.y += c1.y;
            }
            *(float2*)(C + o0) = v0;
            *(float2*)(C + o1) = v1;
        }
    }
}

// =====================================================================
// Flash attention, fp16 mma. 4 warps, 64 q-rows per CTA, 64-key chunks.
// Q prescaled by 1/8. Qs/Ks: [row][d] halves; Vs: [key][d], read via
// ldmatrix.x2.trans for the PV b-fragments.
// =====================================================================
#define ALDS 72   // padded row stride in halves (64 data + 8 pad)

__global__ void __launch_bounds__(128) attn_mma(
    const float* __restrict__ Q, const float* __restrict__ K,
    const float* __restrict__ V, float* __restrict__ O)
{
    __shared__ __half Qs[64 * ALDS];
    __shared__ __half Ks[64 * ALDS];
    __shared__ __half Vs[64 * ALDS];

    int tid  = threadIdx.x;
    int lane = tid & 31;
    int warp = tid >> 5;        // m-tile: rows warp*16 .. +15
    int g  = lane >> 2;
    int t4 = lane & 3;
    int h  = blockIdx.y;
    int q0 = blockIdx.x * 64;

    // ---- load Q tile (prescaled by 1/8), fp32 -> fp16 ----
    #pragma unroll
    for (int i = 0; i < 8; i++) {
        int f = tid + i * 128;          // 0..1023
        int r = f >> 4;
        int c = (f & 15) * 4;
        float4 t = *(const float4*)(Q + (size_t)(q0 + r) * DIM + h * HD + c);
        uint2 u;
        u.x = pack_h2(t.x * 0.125f, t.y * 0.125f);
        u.y = pack_h2(t.z * 0.125f, t.w * 0.125f);
        *(uint2*)&Qs[r * ALDS + c] = u;
    }
    __syncthreads();

    // ---- hoist Q a-fragments into registers (loop invariant) ----
    uint32_t qf[4][4];
    {
        int rbse = warp * 16;
        #pragma unroll
        for (int ks = 0; ks < 4; ks++) {
            qf[ks][0] = *(uint32_t*)&Qs[(rbse + g    ) * ALDS + ks * 16     + 2 * t4];
            qf[ks][1] = *(uint32_t*)&Qs[(rbse + g + 8) * ALDS + ks * 16     + 2 * t4];
            qf[ks][2] = *(uint32_t*)&Qs[(rbse + g    ) * ALDS + ks * 16 + 8 + 2 * t4];
            qf[ks][3] = *(uint32_t*)&Qs[(rbse + g + 8) * ALDS + ks * 16 + 8 + 2 * t4];
        }
    }

    float oacc[8][4];
    #pragma unroll
    for (int nd = 0; nd < 8; nd++)
        #pragma unroll
        for (int c = 0; c < 4; c++) oacc[nd][c] = 0.f;
    float m0 = -1e30f, m1 = -1e30f, l0 = 0.f, l1 = 0.f;

    for (int kt = 0; kt < SEQ; kt += 64) {
        __syncthreads();
        // ---- stage K, V chunk ----
        #pragma unroll
        for (int i = 0; i < 8; i++) {
            int f = tid + i * 128;
            int r = f >> 4;
            int c = (f & 15) * 4;
            size_t goff = (size_t)(kt + r) * DIM + h * HD + c;
            float4 tk = *(const float4*)(K + goff);
            float4 tv = *(const float4*)(V + goff);
            uint2 uk, uv;
            uk.x = pack_h2(tk.x, tk.y); uk.y = pack_h2(tk.z, tk.w);
            uv.x = pack_h2(tv.x, tv.y); uv.y = pack_h2(tv.z, tv.w);
            *(uint2*)&Ks[r * ALDS + c] = uk;
            *(uint2*)&Vs[r * ALDS + c] = uv;
        }
        __syncthreads();

        // ---- S = Q K^T (scaled) ----
        float sacc[8][4];
        #pragma unroll
        for (int nj = 0; nj < 8; nj++)
            #pragma unroll
            for (int c = 0; c < 4; c++) sacc[nj][c] = 0.f;

        #pragma unroll
        for (int ks = 0; ks < 4; ks++) {
            #pragma unroll
            for (int nj = 0; nj < 8; nj++) {
                int nb = nj * 8;
                uint32_t b0 = *(uint32_t*)&Ks[(nb + g) * ALDS + ks * 16     + 2 * t4];
                uint32_t b1 = *(uint32_t*)&Ks[(nb + g) * ALDS + ks * 16 + 8 + 2 * t4];
                mma16816(sacc[nj], qf[ks][0], qf[ks][1], qf[ks][2], qf[ks][3], b0, b1);
            }
        }

        // ---- online softmax ----
        float mx0 = -1e30f, mx1 = -1e30f;
        #pragma unroll
        for (int nj = 0; nj < 8; nj++) {
            mx0 = fmaxf(mx0, fmaxf(sacc[nj][0], sacc[nj][1]));
            mx1 = fmaxf(mx1, fmaxf(sacc[nj][2], sacc[nj][3]));
        }
        mx0 = fmaxf(mx0, __shfl_xor_sync(0xffffffffu, mx0, 1));
        mx0 = fmaxf(mx0, __shfl_xor_sync(0xffffffffu, mx0, 2));
        mx1 = fmaxf(mx1, __shfl_xor_sync(0xffffffffu, mx1, 1));
        mx1 = fmaxf(mx1, __shfl_xor_sync(0xffffffffu, mx1, 2));
        float m0n = fmaxf(m0, mx0);
        float m1n = fmaxf(m1, mx1);
        float sc0 = __expf(m0 - m0n);
        float sc1 = __expf(m1 - m1n);
        l0 *= sc0; l1 *= sc1;
        #pragma unroll
        for (int nd = 0; nd < 8; nd++) {
            oacc[nd][0] *= sc0; oacc[nd][1] *= sc0;
            oacc[nd][2] *= sc1; oacc[nd][3] *= sc1;
        }
        m0 = m0n; m1 = m1n;

        uint32_t ph[8][2];
        #pragma unroll
        for (int nj = 0; nj < 8; nj++) {
            float p0 = __expf(sacc[nj][0] - m0);
            float p1 = __expf(sacc[nj][1] - m0);
            float p2 = __expf(sacc[nj][2] - m1);
            float p3 = __expf(sacc[nj][3] - m1);
            l0 += p0 + p1;
            l1 += p2 + p3;
            ph[nj][0] = pack_h2(p0, p1);
            ph[nj][1] = pack_h2(p2, p3);
        }

        // ---- O += P V ----
        uint32_t vbase = (uint32_t)__cvta_generic_to_shared(Vs);
        #pragma unroll
        for (int kk = 0; kk < 4; kk++) {
            uint32_t rowadr = vbase + (uint32_t)((kk * 16 + (lane & 15)) * ALDS) * 2u;
            #pragma unroll
            for (int nd = 0; nd < 8; nd++) {
                uint32_t b0, b1;
                asm volatile(
                    "ldmatrix.sync.aligned.m8n8.x2.trans.shared.b16 {%0,%1}, [%2];"
                    : "=r"(b0), "=r"(b1)
                    : "r"(rowadr + (uint32_t)(nd * 16)));
                mma16816(oacc[nd], ph[2 * kk][0], ph[2 * kk][1],
                         ph[2 * kk + 1][0], ph[2 * kk + 1][1], b0, b1);
            }
        }
    }

    // ---- finalize ----
    l0 += __shfl_xor_sync(0xffffffffu, l0, 1);
    l0 += __shfl_xor_sync(0xffffffffu, l0, 2);
    l1 += __shfl_xor_sync(0xffffffffu, l1, 1);
    l1 += __shfl_xor_sync(0xffffffffu, l1, 2);
    float i0 = 1.f / l0, i1 = 1.f / l1;

    size_t r0 = (size_t)(q0 + warp * 16 + g);
    #pragma unroll
    for (int nd = 0; nd < 8; nd++) {
        size_t col = (size_t)(h * HD + nd * 8 + 2 * t4);
        float2 v0, v1;
        v0.x = oacc[nd][0] * i0; v0.y = oacc[nd][1] * i0;
        v1.x = oacc[nd][2] * i1; v1.y = oacc[nd][3] * i1;
        *(float2*)(O + r0 * DIM + col)       = v0;
        *(float2*)(O + (r0 + 8) * DIM + col) = v1;
    }
}

// ---------------- rmsnorm: one block per row ----------------
__global__ void rmsnorm_kernel(const float* __restrict__ x,
                               const float* __restrict__ g,
                               float* __restrict__ o)
{
    int row = blockIdx.x;
    int tid = threadIdx.x;                       // 256 threads, 4 floats each
    const float4* xr = (const float4*)(x + (size_t)row * DIM);
    float4 v = xr[tid];
    float s = v.x * v.x + v.y * v.y + v.z * v.z + v.w * v.w;
    #pragma unroll
    for (int off = 16; off; off >>= 1) s += __shfl_xor_sync(0xffffffffu, s, off);

    __shared__ float red[8];
    __shared__ float rinv;
    if ((tid & 31) == 0) red[tid >> 5] = s;
    __syncthreads();
    if (tid == 0) {
        float t = 0.f;
        #pragma unroll
        for (int i = 0; i < 8; i++) t += red[i];
        rinv = rsqrtf(t / (float)DIM + EPSV);
    }
    __syncthreads();
    float r = rinv;
    const float4* gr = (const float4*)g;
    float4 gv = gr[tid];
    float4 ov;
    ov.x = v.x * r * gv.x;
    ov.y = v.y * r * gv.y;
    ov.z = v.z * r * gv.z;
    ov.w = v.w * r * gv.w;
    ((float4*)(o + (size_t)row * DIM))[tid] = ov;
}

// ---------------- RoPE (in-place on q and k) ----------------
__global__ void rope_kernel(float* __restrict__ q, float* __restrict__ k)
{
    int idx = blockIdx.x * blockDim.x + threadIdx.x;   // SEQ*NH*32 total
    int i = idx & 31;            // pair index 0..31
    int h = (idx >> 5) & (NH - 1);
    int s = idx >> 9;
    float inv = (float)pow(10000.0, -(double)(2 * i) / (double)HD);
    float ang = (float)s * inv;
    float c, sn;
    sincosf(ang, &sn, &c);
    size_t base = (size_t)s * DIM + h * HD + 2 * i;
    float qr = q[base], qi = q[base + 1];
    q[base]     = qr * c - qi * sn;
    q[base + 1] = qr * sn + qi * c;
    float kr = k[base], ki = k[base + 1];
    k[base]     = kr * c - ki * sn;
    k[base + 1] = kr * sn + ki * c;
}

// ---------------- swiglu: g1 = silu(g1) * g3 ----------------
__global__ void swiglu_kernel(float* __restrict__ g1, const float* __restrict__ g3)
{
    int i = blockIdx.x * blockDim.x + threadIdx.x;
    float4 a = ((const float4*)g1)[i];
    float4 b = ((const float4*)g3)[i];
    float4 o;
    o.x = a.x / (1.f + __expf(-a.x)) * b.x;
    o.y = a.y / (1.f + __expf(-a.y)) * b.y;
    o.z = a.z / (1.f + __expf(-a.z)) * b.z;
    o.w = a.w / (1.f + __expf(-a.w)) * b.w;
    ((float4*)g1)[i] = o;
}

// ---------------- launch ----------------
extern "C" void kernel_launch(void* const* d_in, const int* in_sizes, int n_in,
                              void* d_out, int out_size)
{
    const float* x  = (const float*)d_in[0];
    const float* wq = (const float*)d_in[1];
    const float* wk = (const float*)d_in[2];
    const float* wv = (const float*)d_in[3];
    const float* wo = (const float*)d_in[4];
    const float* w1 = (const float*)d_in[5];
    const float* w2 = (const float*)d_in[6];
    const float* w3 = (const float*)d_in[7];
    const float* ga = (const float*)d_in[8];
    const float* gf = (const float*)d_in[9];
    float* out = (float*)d_out;

    float *xn, *q, *k, *v, *attn, *h, *hn, *g1, *g3;
    cudaGetSymbolAddress((void**)&xn,   d_xn);
    cudaGetSymbolAddress((void**)&q,    d_q);
    cudaGetSymbolAddress((void**)&k,    d_k);
    cudaGetSymbolAddress((void**)&v,    d_v);
    cudaGetSymbolAddress((void**)&attn, d_attn);
    cudaGetSymbolAddress((void**)&h,    d_h);
    cudaGetSymbolAddress((void**)&hn,   d_hn);
    cudaGetSymbolAddress((void**)&g1,   d_g1);
    cudaGetSymbolAddress((void**)&g3,   d_g3);

    // 1. rmsnorm(x) -> xn
    rmsnorm_kernel<<<SEQ, 256>>>(x, ga, xn);

    // 2. q/k/v projections (fp16 tensor cores, fp32 accumulate)
    dim3 gproj(DIM / 128, SEQ / 128);
    gemm_f16<<<gproj, 256>>>(xn, wq, nullptr, q, DIM, DIM);
    gemm_f16<<<gproj, 256>>>(xn, wk, nullptr, k, DIM, DIM);
    gemm_f16<<<gproj, 256>>>(xn, wv, nullptr, v, DIM, DIM);

    // 3. RoPE in place
    rope_kernel<<<(SEQ * NH * (HD / 2)) / 256, 256>>>(q, k);

    // 4. attention (fp16 mma flash attention)
    dim3 gattn(SEQ / 64, NH);
    attn_mma<<<gattn, 128>>>(q, k, v, attn);

    // 5. output projection + residual: h = x + attn @ wo^T
    gemm_f16<<<gproj, 256>>>(attn, wo, x, h, DIM, DIM);

    // 6. rmsnorm(h) -> hn
    rmsnorm_kernel<<<SEQ, 256>>>(h, gf, hn);

    // 7. FFN up projections
    dim3 gffn(HIDDEN / 128, SEQ / 128);
    gemm_f16<<<gffn, 256>>>(hn, w1, nullptr, g1, HIDDEN, DIM);
    gemm_f16<<<gffn, 256>>>(hn, w3, nullptr, g3, HIDDEN, DIM);

    // 8. swiglu gate
    swiglu_kernel<<<(SEQ * HIDDEN) / (256 * 4), 256>>>(g1, g3);

    // 9. down projection + residual: out = h + g1 @ w2^T
    gemm_f16<<<gproj, 256>>>(g1, w2, h, out, DIM, HIDDEN);
}